// round 1
// baseline (speedup 1.0000x reference)
#include <cuda_runtime.h>
#include <cstdint>

// Problem constants: sim is 8192 x 8192 fp32.
#define BDIM 8192
#define TILE_C 128          // columns per block tile
#define TILE_R 256          // rows per block tile
#define NCS (BDIM / TILE_C) // 64 column stripes
#define NRS (BDIM / TILE_R) // 32 row stripes
#define K2_BLOCKS (BDIM / 256) // 32

#define NEG_INF __int_as_float(0xff800000)

// Scratch (allocation-free rule: use __device__ globals).
__device__ float g_rowpart[NCS * BDIM];   // [col-stripe][row]  (2 MB)
__device__ float g_colpart[NRS * BDIM];   // [row-stripe][col]  (1 MB)
__device__ float g_blocksum[K2_BLOCKS];

// ---------------------------------------------------------------------------
// K1: single pass over the matrix. Each block owns a TILE_R x TILE_C tile.
// blockDim = (32, 8): a warp (32 lanes x float4) spans the 128-col tile width,
// 8 warps cover 8 rows concurrently, looping TILE_R/8 = 32 iterations.
// Produces per-stripe row maxes and col maxes (diagonal excluded).
// ---------------------------------------------------------------------------
__global__ void __launch_bounds__(256) wtl_k1(const float* __restrict__ sim) {
    const int tx = threadIdx.x;            // 0..31
    const int ty = threadIdx.y;            // 0..7
    const int colBase = blockIdx.x * TILE_C;
    const int rowBase = blockIdx.y * TILE_R;
    const int gcol0 = colBase + tx * 4;

    float cm0 = NEG_INF, cm1 = NEG_INF, cm2 = NEG_INF, cm3 = NEG_INF;

    __shared__ float s_col[8][TILE_C];

    #pragma unroll 4
    for (int r = ty; r < TILE_R; r += 8) {
        const int grow = rowBase + r;
        const float4 v = *reinterpret_cast<const float4*>(
            sim + (size_t)grow * BDIM + gcol0);

        // Exclude the diagonal element from both reductions.
        const float e0 = (grow == gcol0 + 0) ? NEG_INF : v.x;
        const float e1 = (grow == gcol0 + 1) ? NEG_INF : v.y;
        const float e2 = (grow == gcol0 + 2) ? NEG_INF : v.z;
        const float e3 = (grow == gcol0 + 3) ? NEG_INF : v.w;

        cm0 = fmaxf(cm0, e0);
        cm1 = fmaxf(cm1, e1);
        cm2 = fmaxf(cm2, e2);
        cm3 = fmaxf(cm3, e3);

        float rmax = fmaxf(fmaxf(e0, e1), fmaxf(e2, e3));
        #pragma unroll
        for (int o = 16; o > 0; o >>= 1)
            rmax = fmaxf(rmax, __shfl_xor_sync(0xffffffffu, rmax, o));
        if (tx == 0)
            g_rowpart[(size_t)blockIdx.x * BDIM + grow] = rmax;
    }

    // Column-max: reduce the 8 warp-rows' per-thread col maxes via shared mem.
    s_col[ty][tx * 4 + 0] = cm0;
    s_col[ty][tx * 4 + 1] = cm1;
    s_col[ty][tx * 4 + 2] = cm2;
    s_col[ty][tx * 4 + 3] = cm3;
    __syncthreads();

    const int tid = ty * 32 + tx;
    if (tid < TILE_C) {
        float m = s_col[0][tid];
        #pragma unroll
        for (int s = 1; s < 8; s++) m = fmaxf(m, s_col[s][tid]);
        g_colpart[(size_t)blockIdx.y * BDIM + colBase + tid] = m;
    }
}

// ---------------------------------------------------------------------------
// K2: per index i, fold stripe partials -> rowmax/colmax, read diag, compute
// the two half-losses, block-reduce the sum. 32 blocks x 256 threads.
// ---------------------------------------------------------------------------
__global__ void __launch_bounds__(256) wtl_k2(const float* __restrict__ sim) {
    const int i = blockIdx.x * 256 + threadIdx.x;

    const float pos = sim[(size_t)i * BDIM + i];

    float rm = NEG_INF;
    #pragma unroll
    for (int s = 0; s < NCS; s++)
        rm = fmaxf(rm, g_rowpart[(size_t)s * BDIM + i]);

    float cm = NEG_INF;
    #pragma unroll
    for (int s = 0; s < NRS; s++)
        cm = fmaxf(cm, g_colpart[(size_t)s * BDIM + i]);

    const float pos_loss = fmaxf(0.2f * pos * pos - 0.7f * pos + 0.5f, 0.0f);

    float total = 0.0f;
    if (rm + 1.0f > pos) {  // strict, matches mat + MARGIN > pos
        total += pos_loss + fmaxf(0.9f * rm * rm - 0.4f * rm + 0.03f, 0.0f);
    }
    if (cm + 1.0f > pos) {
        total += pos_loss + fmaxf(0.9f * cm * cm - 0.4f * cm + 0.03f, 0.0f);
    }

    __shared__ float s_sum[256];
    s_sum[threadIdx.x] = total;
    __syncthreads();
    #pragma unroll
    for (int s = 128; s > 0; s >>= 1) {
        if (threadIdx.x < s) s_sum[threadIdx.x] += s_sum[threadIdx.x + s];
        __syncthreads();
    }
    if (threadIdx.x == 0) g_blocksum[blockIdx.x] = s_sum[0];
}

// ---------------------------------------------------------------------------
// K3: deterministic final fold of 32 block sums; writes the scalar output.
// ---------------------------------------------------------------------------
__global__ void wtl_k3(float* __restrict__ out) {
    float v = g_blocksum[threadIdx.x];  // 32 threads
    #pragma unroll
    for (int o = 16; o > 0; o >>= 1)
        v += __shfl_xor_sync(0xffffffffu, v, o);
    if (threadIdx.x == 0) out[0] = v / (float)BDIM;
}

extern "C" void kernel_launch(void* const* d_in, const int* in_sizes, int n_in,
                              void* d_out, int out_size) {
    const float* sim = (const float*)d_in[0];
    float* out = (float*)d_out;

    dim3 grid1(BDIM / TILE_C, BDIM / TILE_R);  // (64, 32)
    dim3 block1(32, 8);
    wtl_k1<<<grid1, block1>>>(sim);
    wtl_k2<<<K2_BLOCKS, 256>>>(sim);
    wtl_k3<<<1, 32>>>(out);
}